// round 7
// baseline (speedup 1.0000x reference)
#include <cuda_runtime.h>
#include <cuda_bf16.h>
#include <cstddef>
#include <cstdint>

// Problem constants
#define TT     1024
#define BBATCH 128
#define DD     128
#define HH     256
#define RTOT   (TT * BBATCH)   /* 131072 flat rows */
#define G4H    1024            /* 4*H gate columns */
#define SPAD   260             /* padded SMEM row stride (floats) */
#define BKC    64              /* GEMM K chunk in bf16 elements (128B rows) */

typedef unsigned long long ull;

// ---------------------------------------------------------------------------
// Scratch (static device globals — no allocation APIs allowed)
// g_xg layout is PERMUTED for scan-side coalescing:
//   element (flat row r, gate col n) lives at ((n>>4)*RTOT + r)*16 + (n&15)
// ---------------------------------------------------------------------------
__device__ float g_xg[(size_t)RTOT * G4H];   // 512 MB gate staging (permuted)
__device__ float g_tmp[(size_t)RTOT * HH];   // 128 MB inter-layer activations
__device__ __align__(256) __nv_bfloat16 g_Ah[(size_t)RTOT * HH]; // 64 MB
__device__ __align__(256) __nv_bfloat16 g_Al[(size_t)RTOT * HH]; // 64 MB
__device__ __align__(256) __nv_bfloat16 g_Wh[1024 * HH];
__device__ __align__(256) __nv_bfloat16 g_Wl[1024 * HH];

// ---------------------------------------------------------------------------
// Helpers (portable PTX only: compute_103 generic target, sm_90 baseline)
// ---------------------------------------------------------------------------
__device__ __forceinline__ void fma2(ull& d, ull a, ull b) {
    asm("fma.rn.f32x2 %0, %1, %2, %0;" : "+l"(d) : "l"(a), "l"(b));
}
__device__ __forceinline__ float2 unpack2(ull v) {
    unsigned lo, hi;
    asm("mov.b64 {%0, %1}, %2;" : "=r"(lo), "=r"(hi) : "l"(v));
    return make_float2(__uint_as_float(lo), __uint_as_float(hi));
}
__device__ __forceinline__ float sigf(float x) {
    return __fdividef(1.f, 1.f + __expf(-x));
}
__device__ __forceinline__ float tanh_fast(float x) {
    return 2.f * sigf(2.f * x) - 1.f;
}
__device__ __forceinline__ uint32_t smem_u32(const void* p) {
    uint32_t a;
    asm("{ .reg .u64 t; cvta.to.shared.u64 t, %1; cvt.u32.u64 %0, t; }"
        : "=r"(a) : "l"(p));
    return a;
}
__device__ __forceinline__ uint32_t mapa_u32(uint32_t addr, uint32_t rank) {
    uint32_t r;
    asm("mapa.shared::cluster.u32 %0, %1, %2;" : "=r"(r) : "r"(addr), "r"(rank));
    return r;
}
__device__ __forceinline__ void st_cluster_f32(uint32_t addr, float v) {
    asm volatile("st.shared::cluster.f32 [%0], %1;" :: "r"(addr), "f"(v)
                 : "memory");
}
__device__ __forceinline__ void mbar_arrive_cluster(uint32_t remote_addr) {
    asm volatile("mbarrier.arrive.shared::cluster.b64 _, [%0];"
                 :: "r"(remote_addr) : "memory");
}
__device__ __forceinline__ void mbar_wait_cluster(uint32_t addr, unsigned parity) {
    asm volatile(
        "{\n\t.reg .pred P;\n\t"
        "WL%=:\n\t"
        "mbarrier.try_wait.parity.acquire.cluster.shared::cta.b64 P, [%0], %1, 0x989680;\n\t"
        "@P bra WD%=;\n\t"
        "bra WL%=;\n\t"
        "WD%=:\n\t}"
        :: "r"(addr), "r"(parity) : "memory");
}
#define SWZ(o) ((o) ^ (((o) >> 3) & 0x70))
__device__ __forceinline__ void cp16(uint32_t dst, const void* src) {
    asm volatile("cp.async.cg.shared.global [%0], [%1], 16;"
                 :: "r"(dst), "l"(src) : "memory");
}
__device__ __forceinline__ void ldm4(uint32_t* r, uint32_t addr) {
    asm volatile("ldmatrix.sync.aligned.m8n8.x4.shared.b16 {%0,%1,%2,%3}, [%4];"
                 : "=r"(r[0]), "=r"(r[1]), "=r"(r[2]), "=r"(r[3]) : "r"(addr));
}
__device__ __forceinline__ void mma_bf16(float* d, const uint32_t* a,
                                         const uint32_t* b) {
    asm volatile(
        "mma.sync.aligned.m16n8k16.row.col.f32.bf16.bf16.f32 "
        "{%0,%1,%2,%3}, {%4,%5,%6,%7}, {%8,%9}, {%0,%1,%2,%3};"
        : "+f"(d[0]), "+f"(d[1]), "+f"(d[2]), "+f"(d[3])
        : "r"(a[0]), "r"(a[1]), "r"(a[2]), "r"(a[3]), "r"(b[0]), "r"(b[1]));
}

// ---------------------------------------------------------------------------
// Split-conversion: fp32 -> (bf16 hi, bf16 lo). n4 = element count / 4.
// ---------------------------------------------------------------------------
__global__ void __launch_bounds__(256) convert_split_kernel(
    const float* __restrict__ src, __nv_bfloat16* __restrict__ hi,
    __nv_bfloat16* __restrict__ lo, int n4)
{
    int i = blockIdx.x * blockDim.x + threadIdx.x;
    if (i >= n4) return;
    float4 v = ((const float4*)src)[i];
    __nv_bfloat16 h0 = __float2bfloat16(v.x);
    __nv_bfloat16 h1 = __float2bfloat16(v.y);
    __nv_bfloat16 h2 = __float2bfloat16(v.z);
    __nv_bfloat16 h3 = __float2bfloat16(v.w);
    __nv_bfloat16 l0 = __float2bfloat16(v.x - __bfloat162float(h0));
    __nv_bfloat16 l1 = __float2bfloat16(v.y - __bfloat162float(h1));
    __nv_bfloat16 l2 = __float2bfloat16(v.z - __bfloat162float(h2));
    __nv_bfloat16 l3 = __float2bfloat16(v.w - __bfloat162float(h3));
    ((__nv_bfloat162*)hi)[2 * i]     = __nv_bfloat162(h0, h1);
    ((__nv_bfloat162*)hi)[2 * i + 1] = __nv_bfloat162(h2, h3);
    ((__nv_bfloat162*)lo)[2 * i]     = __nv_bfloat162(l0, l1);
    ((__nv_bfloat162*)lo)[2 * i + 1] = __nv_bfloat162(l2, l3);
}

// ---------------------------------------------------------------------------
// HMMA bf16-split GEMM (unchanged — proven).
// xg[r][n] = sum_k A[r][k]*W[n][k] + bih[n]+bhh[n], output PERMUTED.
// ---------------------------------------------------------------------------
template <int K>
__global__ void __launch_bounds__(256) gemm_hmma_kernel(
    const float* __restrict__ bih, const float* __restrict__ bhh)
{
    extern __shared__ char smem[];
    const uint32_t abase = (smem_u32(smem) + 1023u) & ~1023u;

    const int tid  = threadIdx.x;
    const int wid  = tid >> 5;
    const int lane = tid & 31;
    const int col0 = blockIdx.x * 128;
    const int row0 = blockIdx.y * 128;
    const int wm   = wid & 1;
    const int wn   = wid >> 1;

    const __nv_bfloat16* Aop[3] = {g_Ah, g_Al, g_Ah};
    const __nv_bfloat16* Bop[3] = {g_Wh, g_Wh, g_Wl};
    constexpr int KCH = K / BKC;
    constexpr int NC  = 3 * KCH;

    auto prefetch = [&](int c) {
        const int pass = c / KCH;
        const int kc   = c % KCH;
        const __nv_bfloat16* A = Aop[pass];
        const __nv_bfloat16* B = Bop[pass];
        const uint32_t bufA = abase + (uint32_t)(c & 1) * 32768u;
        const uint32_t bufB = bufA + 16384u;
#pragma unroll
        for (int i = 0; i < 4; ++i) {
            int ch = tid + i * 256;
            int r  = ch >> 3;
            int cc = ch & 7;
            uint32_t off = SWZ((uint32_t)(r * 128 + cc * 16));
            cp16(bufA + off, A + (size_t)(row0 + r) * K + kc * BKC + cc * 8);
            cp16(bufB + off, B + (size_t)(col0 + r) * K + kc * BKC + cc * 8);
        }
        asm volatile("cp.async.commit_group;" ::: "memory");
    };

    float acc[4][4][4];
#pragma unroll
    for (int mt = 0; mt < 4; ++mt)
#pragma unroll
        for (int nt = 0; nt < 4; ++nt)
#pragma unroll
            for (int i = 0; i < 4; ++i) acc[mt][nt][i] = 0.f;

    prefetch(0);

    for (int c = 0; c < NC; ++c) {
        if (c + 1 < NC) {
            prefetch(c + 1);
            asm volatile("cp.async.wait_group 1;" ::: "memory");
        } else {
            asm volatile("cp.async.wait_group 0;" ::: "memory");
        }
        __syncthreads();

        const uint32_t bufA = abase + (uint32_t)(c & 1) * 32768u;
        const uint32_t bufB = bufA + 16384u;

#pragma unroll
        for (int ks = 0; ks < 4; ++ks) {
            uint32_t afr[4][4];
            {
                int arow = wm * 64 + (lane & 15);
                int kb   = ks * 32 + (lane >> 4) * 16;
#pragma unroll
                for (int mt = 0; mt < 4; ++mt)
                    ldm4(afr[mt],
                         bufA + SWZ((uint32_t)((arow + mt * 16) * 128 + kb)));
            }
            uint32_t bfr[4][2];
            {
                int j    = lane >> 3;
                int brow = (j >> 1) * 8 + (lane & 7);
                int kb   = ks * 32 + (j & 1) * 16;
#pragma unroll
                for (int p = 0; p < 2; ++p) {
                    uint32_t r[4];
                    ldm4(r, bufB +
                            SWZ((uint32_t)((wn * 32 + p * 16 + brow) * 128 + kb)));
                    bfr[p * 2][0]     = r[0];
                    bfr[p * 2][1]     = r[1];
                    bfr[p * 2 + 1][0] = r[2];
                    bfr[p * 2 + 1][1] = r[3];
                }
            }
#pragma unroll
            for (int mt = 0; mt < 4; ++mt)
#pragma unroll
                for (int nt = 0; nt < 4; ++nt)
                    mma_bf16(acc[mt][nt], afr[mt], bfr[nt]);
        }
        __syncthreads();
    }

#pragma unroll
    for (int nt = 0; nt < 4; ++nt) {
        int n0 = col0 + wn * 32 + nt * 8 + (lane & 3) * 2;
        float b0 = bih[n0] + bhh[n0];
        float b1 = bih[n0 + 1] + bhh[n0 + 1];
        size_t plane = (size_t)(n0 >> 4) * RTOT;
        int cc = n0 & 15;
#pragma unroll
        for (int mt = 0; mt < 4; ++mt) {
            int r0 = row0 + wm * 64 + mt * 16 + (lane >> 2);
            float2 v0 = make_float2(acc[mt][nt][0] + b0, acc[mt][nt][1] + b1);
            float2 v1 = make_float2(acc[mt][nt][2] + b0, acc[mt][nt][3] + b1);
            *(float2*)&g_xg[(plane + r0) * 16 + cc]     = v0;
            *(float2*)&g_xg[(plane + r0 + 8) * 16 + cc] = v1;
        }
    }
}

// ---------------------------------------------------------------------------
// Cluster-DSMEM persistent scan. Cluster of 8 blocks = one row group; block
// rank cg owns CW=32 h-columns (W slice 128KB fp32 in SMEM), RW contiguous
// rows. h lives in DOUBLE-BUFFERED local SMEM (Hsm[2]); each step every block
// PUSHES its h slice into all 8 cluster peers' next-buffer via
// st.shared::cluster, then one elected thread arrives on every peer's
// mbarrier (count 8). Next step begins with a local-SMEM mbarrier wait —
// no L2 round trips, no polling storm, no h staging loop.
// KS=2 (layer 0): pairs of threads split the k-dim, combined via shfl.
// ---------------------------------------------------------------------------
template <int MB, int RW, int RPT, int KS>
__global__ void __launch_bounds__(512, 1) __cluster_dims__(8, 1, 1)
scan_kernel(const float* __restrict__ Whh, float* __restrict__ out, int nsteps)
{
    constexpr int CW  = 32;
    constexpr int NCG = 8;
    constexpr int CWP = 36;

    extern __shared__ float smemf[];
    const uint32_t sbase = smem_u32(smemf);
    const uint32_t mbA   = sbase;                    // 8B mbarrier
    float* Wsm = smemf + 8;                          // [4*CW][SPAD]
    float* Hsm = Wsm + 4 * CW * SPAD;                // [2][RW][SPAD]
    float* Xsm = Hsm + 2 * RW * SPAD;                // [4][RW][CWP]
    float* Ssm = Xsm + 4 * RW * CWP;                 // [RW][CWP]
    const uint32_t hsm_u32 = smem_u32(Hsm);

    const int tid     = threadIdx.x;
    const int cg      = blockIdx.x & 7;              // cluster rank
    const int rg      = blockIdx.x >> 3;
    const int gc0     = cg * CW;
    const int rowbase = rg * RW;
    const int c       = tid >> 4;                    // owned column 0..31
    const int slot    = tid & 15;
    const int q       = (KS == 2) ? (slot & 7) : slot;
    const int khalf   = (KS == 2) ? (slot >> 3) : 0;
    const int k4b     = (KS == 2) ? khalf * 32 : 0;
    const int k4n     = (KS == 2) ? 32 : 64;

    if (tid == 0) {
        asm volatile("mbarrier.init.shared.b64 [%0], %1;"
                     :: "r"(mbA), "r"((unsigned)NCG) : "memory");
    }

    // Stage W slice: Wsm[g*CW+cc][k] = Whh[g*256 + gc0 + cc][k]
    for (int idx = tid; idx < 4 * CW * 64; idx += 512) {
        int k4 = idx & 63;
        int cc = (idx >> 6) & 31;
        int g  = idx >> 11;
        float4 v = *(const float4*)&Whh[(size_t)(g * 256 + gc0 + cc) * HH + k4 * 4];
        *(float4*)&Wsm[(g * CW + cc) * SPAD + k4 * 4] = v;
    }
    // Stage step-0 seeds (permuted g_xg: planes cg*2, cg*2+1 per gate)
    for (int idx = tid; idx < 32 * RW; idx += 512) {
        int c4   = idx & 3;
        int r    = (idx >> 2) % RW;
        int rest = idx / (4 * RW);
        int pl   = rest & 1;
        int g    = rest >> 1;
        const float* src =
            &g_xg[((size_t)(g * 16 + cg * 2 + pl) * RTOT + rowbase + r) * 16 + c4 * 4];
        float4 v = *(const float4*)src;
        float* dst = &Xsm[(g * RW + r) * CWP + pl * 16 + c4 * 4];
        dst[0] = v.x; dst[1] = v.y; dst[2] = v.z; dst[3] = v.w;
    }
    __syncthreads();
    // One-time cluster handshake: all mbarriers initialized before any arrive.
    asm volatile("barrier.cluster.arrive.aligned;" ::: "memory");
    asm volatile("barrier.cluster.wait.aligned;" ::: "memory");

    float c_st[RPT];
#pragma unroll
    for (int j = 0; j < RPT; ++j) c_st[j] = 0.f;

    for (int step = 0; step < nsteps; ++step) {
        if (step > 0) mbar_wait_cluster(mbA, (unsigned)((step - 1) & 1));

        const float* Hc = Hsm + (size_t)(step & 1) * RW * SPAD;
        ull acc[RPT][4];
#pragma unroll
        for (int j = 0; j < RPT; ++j)
#pragma unroll
            for (int g = 0; g < 4; ++g) acc[j][g] = 0ull;

        if (step > 0) {
#pragma unroll 2
            for (int k4 = k4b; k4 < k4b + k4n; ++k4) {
                ulonglong2 w[4];
#pragma unroll
                for (int g = 0; g < 4; ++g)
                    w[g] = *(const ulonglong2*)&Wsm[(g * CW + c) * SPAD + k4 * 4];
#pragma unroll
                for (int j = 0; j < RPT; ++j) {
                    ulonglong2 h2 =
                        *(const ulonglong2*)&Hc[(q + j * 16) * SPAD + k4 * 4];
#pragma unroll
                    for (int g = 0; g < 4; ++g) {
                        fma2(acc[j][g], h2.x, w[g].x);
                        fma2(acc[j][g], h2.y, w[g].y);
                    }
                }
            }
        }

        // Reduce f32x2 pairs (+ k-split partner via shfl) and run the cell.
#pragma unroll
        for (int j = 0; j < RPT; ++j) {
            float gate[4];
#pragma unroll
            for (int g = 0; g < 4; ++g) {
                float2 p = unpack2(acc[j][g]);
                float v = p.x + p.y;
                if (KS == 2) v += __shfl_xor_sync(0xFFFFFFFFu, v, 8);
                gate[g] = v;
            }
            if (KS == 1 || khalf == 0) {
                int row = q + j * 16;
                float vi = gate[0] + Xsm[(0 * RW + row) * CWP + c];
                float vf = gate[1] + Xsm[(1 * RW + row) * CWP + c];
                float vg = gate[2] + Xsm[(2 * RW + row) * CWP + c];
                float vo = gate[3] + Xsm[(3 * RW + row) * CWP + c];
                float ig = sigf(vi);
                float fg = sigf(vf);
                float gt = tanh_fast(vg);
                float og = sigf(vo);
                float cc2 = fg * c_st[j] + ig * gt;
                c_st[j] = cc2;
                Ssm[row * CWP + c] = og * tanh_fast(cc2);
            }
        }
        __syncthreads();   // Ssm complete; all Hc/Xsm reads done block-wide

        if (step + 1 < nsteps) {
            // Push h slice into every cluster peer's next Hsm buffer.
            const uint32_t hn =
                hsm_u32 + (uint32_t)(((step + 1) & 1) * RW * SPAD * 4);
#pragma unroll
            for (int rank = 0; rank < NCG; ++rank) {
                uint32_t base = mapa_u32(hn, (uint32_t)rank);
                for (int idx = tid; idx < RW * CW; idx += 512) {
                    int r  = idx >> 5;
                    int cc = idx & 31;
                    st_cluster_f32(base + (uint32_t)((r * SPAD + gc0 + cc) * 4),
                                   Ssm[r * CWP + cc]);
                }
            }
            __syncthreads();   // all pushes issued block-wide
            if (tid == 0) {
#pragma unroll
                for (int rank = 0; rank < NCG; ++rank)
                    mbar_arrive_cluster(mapa_u32(mbA, (uint32_t)rank));
            }
        }

        // Coalesced gmem h store (layer output) from Ssm
        {
            const size_t ob = ((size_t)step * MB + rowbase) * HH + gc0;
            for (int idx = tid; idx < RW * 8; idx += 512) {
                int r  = idx >> 3;
                int c4 = idx & 7;
                const float* s = &Ssm[r * CWP + c4 * 4];
                float4 v = make_float4(s[0], s[1], s[2], s[3]);
                *(float4*)&out[ob + (size_t)r * HH + c4 * 4] = v;
            }
        }
        // Prefetch next step's seeds (hidden behind peers' compute)
        if (step + 1 < nsteps) {
            const size_t srow0 = (size_t)(step + 1) * MB + rowbase;
            for (int idx = tid; idx < 32 * RW; idx += 512) {
                int c4   = idx & 3;
                int r    = (idx >> 2) % RW;
                int rest = idx / (4 * RW);
                int pl   = rest & 1;
                int g    = rest >> 1;
                const float* src =
                    &g_xg[((size_t)(g * 16 + cg * 2 + pl) * RTOT + srow0 + r) * 16
                          + c4 * 4];
                float4 v = *(const float4*)src;
                float* dst = &Xsm[(g * RW + r) * CWP + pl * 16 + c4 * 4];
                dst[0] = v.x; dst[1] = v.y; dst[2] = v.z; dst[3] = v.w;
            }
        }
        __syncthreads();   // Ssm/Xsm stable before next iteration's writes
    }
}

// ---------------------------------------------------------------------------
// kernel_launch: per layer: split-convert A & W -> HMMA GEMM -> cluster scan.
// Graph-capturable, allocation-free, deterministic.
// ---------------------------------------------------------------------------
extern "C" void kernel_launch(void* const* d_in, const int* in_sizes, int n_in,
                              void* d_out, int out_size)
{
    (void)in_sizes; (void)n_in; (void)out_size;
    const float* x    = (const float*)d_in[0];
    const float* Wih0 = (const float*)d_in[1];
    const float* Whh0 = (const float*)d_in[2];
    const float* bih0 = (const float*)d_in[3];
    const float* bhh0 = (const float*)d_in[4];
    const float* Wih1 = (const float*)d_in[5];
    const float* Whh1 = (const float*)d_in[6];
    const float* bih1 = (const float*)d_in[7];
    const float* bhh1 = (const float*)d_in[8];
    const float* Wih2 = (const float*)d_in[9];
    const float* Whh2 = (const float*)d_in[10];
    const float* bih2 = (const float*)d_in[11];
    const float* bhh2 = (const float*)d_in[12];
    float* out = (float*)d_out;

    float* tmp = nullptr;
    cudaGetSymbolAddress((void**)&tmp, g_tmp);
    __nv_bfloat16 *Ah = nullptr, *Al = nullptr, *Wh = nullptr, *Wl = nullptr;
    cudaGetSymbolAddress((void**)&Ah, g_Ah);
    cudaGetSymbolAddress((void**)&Al, g_Al);
    cudaGetSymbolAddress((void**)&Wh, g_Wh);
    cudaGetSymbolAddress((void**)&Wl, g_Wl);

    // Scan SMEM (floats): 8 + 4*32*SPAD + 2*RW*SPAD + 4*RW*36 + RW*36
    const int smem0 = (8 + 4 * 32 * SPAD + 2 * 8 * SPAD + 5 * 8 * 36 + 4 * 8 * 36 - 4 * 8 * 36 + 4 * 8 * 36) * 4;
    // (compute explicitly to avoid arithmetic slip)
    const int sm0 = (8 + 33280 + 2 * 8 * 260 + 4 * 8 * 36 + 8 * 36) * 4;   // 155552
    const int sm1 = (8 + 33280 + 2 * 16 * 260 + 4 * 16 * 36 + 16 * 36) * 4; // 177952
    const int sm2 = (8 + 33280 + 2 * 32 * 260 + 4 * 32 * 36 + 32 * 36) * 4; // 222752
    (void)smem0;
    cudaFuncSetAttribute((const void*)scan_kernel<128, 8, 1, 2>,
                         cudaFuncAttributeMaxDynamicSharedMemorySize, sm0);
    cudaFuncSetAttribute((const void*)scan_kernel<256, 16, 1, 1>,
                         cudaFuncAttributeMaxDynamicSharedMemorySize, sm1);
    cudaFuncSetAttribute((const void*)scan_kernel<512, 32, 2, 1>,
                         cudaFuncAttributeMaxDynamicSharedMemorySize, sm2);

    const int gsm = 1024 + 2 * 32768;
    cudaFuncSetAttribute((const void*)gemm_hmma_kernel<128>,
                         cudaFuncAttributeMaxDynamicSharedMemorySize, gsm);
    cudaFuncSetAttribute((const void*)gemm_hmma_kernel<256>,
                         cudaFuncAttributeMaxDynamicSharedMemorySize, gsm);

    dim3 ggrid(8, 1024);   // 128-col x 128-row tiles over [131072 x 1024]

    // ---- Layer 0: K=128, MB=128, 1024 steps (16 clusters of 8, RW=8)
    {
        int n4a = RTOT * 128 / 4;
        convert_split_kernel<<<(n4a + 255) / 256, 256>>>(x, Ah, Al, n4a);
        int n4w = 1024 * 128 / 4;
        convert_split_kernel<<<(n4w + 255) / 256, 256>>>(Wih0, Wh, Wl, n4w);
        gemm_hmma_kernel<128><<<ggrid, 256, gsm>>>(bih0, bhh0);
        scan_kernel<128, 8, 1, 2><<<128, 512, sm0>>>(Whh0, tmp, 1024);
    }
    // ---- Layer 1: K=256, MB=256, 512 steps (RW=16)
    {
        int n4a = RTOT * 256 / 4;
        convert_split_kernel<<<(n4a + 255) / 256, 256>>>(tmp, Ah, Al, n4a);
        int n4w = 1024 * 256 / 4;
        convert_split_kernel<<<(n4w + 255) / 256, 256>>>(Wih1, Wh, Wl, n4w);
        gemm_hmma_kernel<256><<<ggrid, 256, gsm>>>(bih1, bhh1);
        scan_kernel<256, 16, 1, 1><<<128, 512, sm1>>>(Whh1, tmp, 512);
    }
    // ---- Layer 2: K=256, MB=512, 256 steps (RW=32, RPT=2; final output)
    {
        int n4a = RTOT * 256 / 4;
        convert_split_kernel<<<(n4a + 255) / 256, 256>>>(tmp, Ah, Al, n4a);
        int n4w = 1024 * 256 / 4;
        convert_split_kernel<<<(n4w + 255) / 256, 256>>>(Wih2, Wh, Wl, n4w);
        gemm_hmma_kernel<256><<<ggrid, 256, gsm>>>(bih2, bhh2);
        scan_kernel<512, 32, 2, 1><<<128, 512, sm2>>>(Whh2, out, 256);
    }
}

// round 10
// speedup vs baseline: 1.2677x; 1.2677x over previous
#include <cuda_runtime.h>
#include <cuda_bf16.h>
#include <cstddef>
#include <cstdint>

// Problem constants
#define TT     1024
#define BBATCH 128
#define DD     128
#define HH     256
#define RTOT   (TT * BBATCH)   /* 131072 flat rows */
#define G4H    1024            /* 4*H gate columns */
#define SPAD   260             /* padded SMEM row stride (floats) */
#define BKC    64              /* GEMM K chunk in bf16 elements (128B rows) */

typedef unsigned long long ull;

// ---------------------------------------------------------------------------
// Scratch (static device globals -- no allocation APIs allowed)
// g_xg layout is PERMUTED for scan-side coalescing:
//   element (flat row r, gate col n) lives at ((n>>4)*RTOT + r)*16 + (n&15)
// ---------------------------------------------------------------------------
__device__ float g_xg[(size_t)RTOT * G4H];   // 512 MB gate staging (permuted)
__device__ float g_tmp[(size_t)RTOT * HH];   // 128 MB inter-layer activations
__device__ __align__(256) __nv_bfloat16 g_Ah[(size_t)RTOT * HH]; // 64 MB
__device__ __align__(256) __nv_bfloat16 g_Al[(size_t)RTOT * HH]; // 64 MB
__device__ __align__(256) __nv_bfloat16 g_Wh[1024 * HH];
__device__ __align__(256) __nv_bfloat16 g_Wl[1024 * HH];
// Per-row-group monotone arrival counters; one 128B line per rg (stride 32 u32).
// Zeroed by zero_bar before every scan launch => deterministic across replays.
__device__ __align__(128) unsigned g_rgbar[32 * 32];

// ---------------------------------------------------------------------------
// Helpers (portable PTX only)
// ---------------------------------------------------------------------------
__device__ __forceinline__ void fma2(ull& d, ull a, ull b) {
    asm("fma.rn.f32x2 %0, %1, %2, %0;" : "+l"(d) : "l"(a), "l"(b));
}
__device__ __forceinline__ float2 unpack2(ull v) {
    unsigned lo, hi;
    asm("mov.b64 {%0, %1}, %2;" : "=r"(lo), "=r"(hi) : "l"(v));
    return make_float2(__uint_as_float(lo), __uint_as_float(hi));
}
__device__ __forceinline__ unsigned ld_acq(const unsigned* p) {
    unsigned v;
    asm volatile("ld.acquire.gpu.u32 %0, [%1];" : "=r"(v) : "l"(p) : "memory");
    return v;
}
__device__ __forceinline__ void red_add_release(unsigned* p) {
    asm volatile("red.release.gpu.add.u32 [%0], 1;" :: "l"(p) : "memory");
}
__device__ __forceinline__ float sigf(float x) {
    return __fdividef(1.f, 1.f + __expf(-x));
}
__device__ __forceinline__ float tanh_fast(float x) {
    return 2.f * sigf(2.f * x) - 1.f;
}
__device__ __forceinline__ uint32_t smem_u32(const void* p) {
    uint32_t a;
    asm("{ .reg .u64 t; cvta.to.shared.u64 t, %1; cvt.u32.u64 %0, t; }"
        : "=r"(a) : "l"(p));
    return a;
}
#define SWZ(o) ((o) ^ (((o) >> 3) & 0x70))
__device__ __forceinline__ void cp16(uint32_t dst, const void* src) {
    asm volatile("cp.async.cg.shared.global [%0], [%1], 16;"
                 :: "r"(dst), "l"(src) : "memory");
}
__device__ __forceinline__ void ldm4(uint32_t* r, uint32_t addr) {
    asm volatile("ldmatrix.sync.aligned.m8n8.x4.shared.b16 {%0,%1,%2,%3}, [%4];"
                 : "=r"(r[0]), "=r"(r[1]), "=r"(r[2]), "=r"(r[3]) : "r"(addr));
}
__device__ __forceinline__ void mma_bf16(float* d, const uint32_t* a,
                                         const uint32_t* b) {
    asm volatile(
        "mma.sync.aligned.m16n8k16.row.col.f32.bf16.bf16.f32 "
        "{%0,%1,%2,%3}, {%4,%5,%6,%7}, {%8,%9}, {%0,%1,%2,%3};"
        : "+f"(d[0]), "+f"(d[1]), "+f"(d[2]), "+f"(d[3])
        : "r"(a[0]), "r"(a[1]), "r"(a[2]), "r"(a[3]), "r"(b[0]), "r"(b[1]));
}

// ---------------------------------------------------------------------------
// zero_bar: reset all rg counters (launched before each scan)
// ---------------------------------------------------------------------------
__global__ void zero_bar_kernel() {
    g_rgbar[threadIdx.x] = 0u;
}

// ---------------------------------------------------------------------------
// Split-conversion: fp32 -> (bf16 hi, bf16 lo). n4 = element count / 4.
// ---------------------------------------------------------------------------
__global__ void __launch_bounds__(256) convert_split_kernel(
    const float* __restrict__ src, __nv_bfloat16* __restrict__ hi,
    __nv_bfloat16* __restrict__ lo, int n4)
{
    int i = blockIdx.x * blockDim.x + threadIdx.x;
    if (i >= n4) return;
    float4 v = ((const float4*)src)[i];
    __nv_bfloat16 h0 = __float2bfloat16(v.x);
    __nv_bfloat16 h1 = __float2bfloat16(v.y);
    __nv_bfloat16 h2 = __float2bfloat16(v.z);
    __nv_bfloat16 h3 = __float2bfloat16(v.w);
    __nv_bfloat16 l0 = __float2bfloat16(v.x - __bfloat162float(h0));
    __nv_bfloat16 l1 = __float2bfloat16(v.y - __bfloat162float(h1));
    __nv_bfloat16 l2 = __float2bfloat16(v.z - __bfloat162float(h2));
    __nv_bfloat16 l3 = __float2bfloat16(v.w - __bfloat162float(h3));
    ((__nv_bfloat162*)hi)[2 * i]     = __nv_bfloat162(h0, h1);
    ((__nv_bfloat162*)hi)[2 * i + 1] = __nv_bfloat162(h2, h3);
    ((__nv_bfloat162*)lo)[2 * i]     = __nv_bfloat162(l0, l1);
    ((__nv_bfloat162*)lo)[2 * i + 1] = __nv_bfloat162(l2, l3);
}

// ---------------------------------------------------------------------------
// HMMA bf16-split GEMM (unchanged -- proven).
// xg[r][n] = sum_k A[r][k]*W[n][k] + bih[n]+bhh[n], output PERMUTED.
// ---------------------------------------------------------------------------
template <int K>
__global__ void __launch_bounds__(256) gemm_hmma_kernel(
    const float* __restrict__ bih, const float* __restrict__ bhh)
{
    extern __shared__ char smem[];
    const uint32_t abase = (smem_u32(smem) + 1023u) & ~1023u;

    const int tid  = threadIdx.x;
    const int wid  = tid >> 5;
    const int lane = tid & 31;
    const int col0 = blockIdx.x * 128;
    const int row0 = blockIdx.y * 128;
    const int wm   = wid & 1;
    const int wn   = wid >> 1;

    const __nv_bfloat16* Aop[3] = {g_Ah, g_Al, g_Ah};
    const __nv_bfloat16* Bop[3] = {g_Wh, g_Wh, g_Wl};
    constexpr int KCH = K / BKC;
    constexpr int NC  = 3 * KCH;

    auto prefetch = [&](int c) {
        const int pass = c / KCH;
        const int kc   = c % KCH;
        const __nv_bfloat16* A = Aop[pass];
        const __nv_bfloat16* B = Bop[pass];
        const uint32_t bufA = abase + (uint32_t)(c & 1) * 32768u;
        const uint32_t bufB = bufA + 16384u;
#pragma unroll
        for (int i = 0; i < 4; ++i) {
            int ch = tid + i * 256;
            int r  = ch >> 3;
            int cc = ch & 7;
            uint32_t off = SWZ((uint32_t)(r * 128 + cc * 16));
            cp16(bufA + off, A + (size_t)(row0 + r) * K + kc * BKC + cc * 8);
            cp16(bufB + off, B + (size_t)(col0 + r) * K + kc * BKC + cc * 8);
        }
        asm volatile("cp.async.commit_group;" ::: "memory");
    };

    float acc[4][4][4];
#pragma unroll
    for (int mt = 0; mt < 4; ++mt)
#pragma unroll
        for (int nt = 0; nt < 4; ++nt)
#pragma unroll
            for (int i = 0; i < 4; ++i) acc[mt][nt][i] = 0.f;

    prefetch(0);

    for (int c = 0; c < NC; ++c) {
        if (c + 1 < NC) {
            prefetch(c + 1);
            asm volatile("cp.async.wait_group 1;" ::: "memory");
        } else {
            asm volatile("cp.async.wait_group 0;" ::: "memory");
        }
        __syncthreads();

        const uint32_t bufA = abase + (uint32_t)(c & 1) * 32768u;
        const uint32_t bufB = bufA + 16384u;

#pragma unroll
        for (int ks = 0; ks < 4; ++ks) {
            uint32_t afr[4][4];
            {
                int arow = wm * 64 + (lane & 15);
                int kb   = ks * 32 + (lane >> 4) * 16;
#pragma unroll
                for (int mt = 0; mt < 4; ++mt)
                    ldm4(afr[mt],
                         bufA + SWZ((uint32_t)((arow + mt * 16) * 128 + kb)));
            }
            uint32_t bfr[4][2];
            {
                int j    = lane >> 3;
                int brow = (j >> 1) * 8 + (lane & 7);
                int kb   = ks * 32 + (j & 1) * 16;
#pragma unroll
                for (int p = 0; p < 2; ++p) {
                    uint32_t r[4];
                    ldm4(r, bufB +
                            SWZ((uint32_t)((wn * 32 + p * 16 + brow) * 128 + kb)));
                    bfr[p * 2][0]     = r[0];
                    bfr[p * 2][1]     = r[1];
                    bfr[p * 2 + 1][0] = r[2];
                    bfr[p * 2 + 1][1] = r[3];
                }
            }
#pragma unroll
            for (int mt = 0; mt < 4; ++mt)
#pragma unroll
                for (int nt = 0; nt < 4; ++nt)
                    mma_bf16(acc[mt][nt], afr[mt], bfr[nt]);
        }
        __syncthreads();
    }

#pragma unroll
    for (int nt = 0; nt < 4; ++nt) {
        int n0 = col0 + wn * 32 + nt * 8 + (lane & 3) * 2;
        float b0 = bih[n0] + bhh[n0];
        float b1 = bih[n0 + 1] + bhh[n0 + 1];
        size_t plane = (size_t)(n0 >> 4) * RTOT;
        int cc = n0 & 15;
#pragma unroll
        for (int mt = 0; mt < 4; ++mt) {
            int r0 = row0 + wm * 64 + mt * 16 + (lane >> 2);
            float2 v0 = make_float2(acc[mt][nt][0] + b0, acc[mt][nt][1] + b1);
            float2 v1 = make_float2(acc[mt][nt][2] + b0, acc[mt][nt][3] + b1);
            *(float2*)&g_xg[(plane + r0) * 16 + cc]     = v0;
            *(float2*)&g_xg[(plane + r0 + 8) * 16 + cc] = v1;
        }
    }
}

// ---------------------------------------------------------------------------
// Persistent scan with NG-way row-group interleaving + counter-only barriers.
// CW=32 columns per block (NCG=8 column blocks per row-group). Block =
// (cg, brow); brow serves NG independent row-groups of RW rows each,
// processed alternately so one group's barrier drain overlaps the other's
// compute. Barrier per rg: monotone counter; publish = red.release(+1);
// wait = poll ld.acquire >= 8*step. h exchange through L2 (out buffer).
// ---------------------------------------------------------------------------
template <int MB, int RW, int NG>
__global__ void __launch_bounds__(256, 1) scan_kernel(
    const float* __restrict__ Whh,   // [1024, 256] row-major
    float* __restrict__ out,         // [nsteps*MB, 256]
    int nsteps)
{
    constexpr int CW  = 32;
    constexpr int NCG = 8;
    constexpr int CWP = 36;
    constexpr int RPT = RW / 8;

    extern __shared__ float smemf[];
    float* Wsm = smemf;                       // [4*CW][SPAD]
    float* Hsm = Wsm + 4 * CW * SPAD;         // [NG][RW][SPAD]
    float* Xsm = Hsm + NG * RW * SPAD;        // [NG][4][RW][CWP]
    float* Ssm = Xsm + NG * 4 * RW * CWP;     // [RW][CWP]

    const int tid      = threadIdx.x;
    const int cg       = blockIdx.x % NCG;
    const int brow     = blockIdx.x / NCG;
    const int gc0      = cg * CW;
    const int rowbase0 = brow * (NG * RW);
    const int c        = tid >> 3;            // owned column 0..31
    const int q        = tid & 7;             // row slot 0..7

    // Stage W slice (one-time): Wsm[gg*CW+cc][k] = Whh[gg*256+gc0+cc][k]
    for (int idx = tid; idx < 4 * CW * 64; idx += 256) {
        int k4 = idx & 63;
        int cc = (idx >> 6) & 31;
        int gg = idx >> 11;
        float4 v = *(const float4*)&Whh[(size_t)(gg * 256 + gc0 + cc) * HH + k4 * 4];
        *(float4*)&Wsm[(gg * CW + cc) * SPAD + k4 * 4] = v;
    }
    // Stage step-0 seeds for all groups
#pragma unroll
    for (int g2 = 0; g2 < NG; ++g2) {
        float* Xg = Xsm + g2 * 4 * RW * CWP;
        const int rowb = rowbase0 + g2 * RW;
        for (int idx = tid; idx < 32 * RW; idx += 256) {
            int c4   = idx & 3;
            int r    = (idx >> 2) % RW;
            int rest = idx / (4 * RW);
            int pl   = rest & 1;
            int gg   = rest >> 1;
            const float* src =
                &g_xg[((size_t)(gg * 16 + cg * 2 + pl) * RTOT + rowb + r) * 16 + c4 * 4];
            float4 v = *(const float4*)src;
            float* dst = &Xg[(gg * RW + r) * CWP + pl * 16 + c4 * 4];
            dst[0] = v.x; dst[1] = v.y; dst[2] = v.z; dst[3] = v.w;
        }
    }

    float c_st[NG][RPT];
#pragma unroll
    for (int g2 = 0; g2 < NG; ++g2)
#pragma unroll
        for (int j = 0; j < RPT; ++j) c_st[g2][j] = 0.f;

    for (int step = 0; step < nsteps; ++step) {
#pragma unroll
        for (int g2 = 0; g2 < NG; ++g2) {
            const int  rowb = rowbase0 + g2 * RW;
            unsigned*  genp = &g_rgbar[(brow * NG + g2) * 32];
            float*     Hg   = Hsm + g2 * RW * SPAD;
            float*     Xg   = Xsm + g2 * 4 * RW * CWP;

            if (step > 0) {
                const unsigned target = (unsigned)(NCG * step);
                while ((int)(ld_acq(genp) - target) < 0) { }
                const float* hp = out + ((size_t)(step - 1) * MB + rowb) * HH;
                for (int idx = tid; idx < RW * 64; idx += 256) {
                    int r  = idx >> 6;
                    int k4 = idx & 63;
                    float4 v = *(const float4*)&hp[r * HH + k4 * 4];
                    *(float4*)&Hg[r * SPAD + k4 * 4] = v;
                }
            }
            __syncthreads();   // Hg + Xg ready

            ull acc[RPT][4];
#pragma unroll
            for (int j = 0; j < RPT; ++j)
#pragma unroll
                for (int gg = 0; gg < 4; ++gg) acc[j][gg] = 0ull;

            if (step > 0) {
#pragma unroll 2
                for (int k4 = 0; k4 < 64; ++k4) {
                    ulonglong2 w[4];
#pragma unroll
                    for (int gg = 0; gg < 4; ++gg)
                        w[gg] = *(const ulonglong2*)&Wsm[(gg * CW + c) * SPAD + k4 * 4];
#pragma unroll
                    for (int j = 0; j < RPT; ++j) {
                        ulonglong2 h2 =
                            *(const ulonglong2*)&Hg[(q + j * 8) * SPAD + k4 * 4];
#pragma unroll
                        for (int gg = 0; gg < 4; ++gg) {
                            fma2(acc[j][gg], h2.x, w[gg].x);
                            fma2(acc[j][gg], h2.y, w[gg].y);
                        }
                    }
                }
            }

            // LSTM cell -> Ssm
#pragma unroll
            for (int j = 0; j < RPT; ++j) {
                int row = q + j * 8;
                float2 pi = unpack2(acc[j][0]);
                float2 pf = unpack2(acc[j][1]);
                float2 pg = unpack2(acc[j][2]);
                float2 po = unpack2(acc[j][3]);
                float vi = pi.x + pi.y + Xg[(0 * RW + row) * CWP + c];
                float vf = pf.x + pf.y + Xg[(1 * RW + row) * CWP + c];
                float vg = pg.x + pg.y + Xg[(2 * RW + row) * CWP + c];
                float vo = po.x + po.y + Xg[(3 * RW + row) * CWP + c];
                float ig = sigf(vi);
                float fg = sigf(vf);
                float gt = tanh_fast(vg);
                float og = sigf(vo);
                float cc2 = fg * c_st[g2][j] + ig * gt;
                c_st[g2][j] = cc2;
                Ssm[row * CWP + c] = og * tanh_fast(cc2);
            }
            __syncthreads();   // Ssm ready; Hg/Xg reads done

            // Publish h (layer output AND exchange medium)
            {
                const size_t ob = ((size_t)step * MB + rowb) * HH + gc0;
                for (int idx = tid; idx < RW * 8; idx += 256) {
                    int r  = idx >> 3;
                    int c4 = idx & 7;
                    const float* s = &Ssm[r * CWP + c4 * 4];
                    float4 v = make_float4(s[0], s[1], s[2], s[3]);
                    *(float4*)&out[ob + (size_t)r * HH + c4 * 4] = v;
                }
            }
            __syncthreads();   // all h stores issued

            if (step + 1 < nsteps) {
                if (tid == 0) {
                    __threadfence();
                    red_add_release(genp);
                }
                // Prefetch this group's next-step seeds (barrier-drain shadow)
                const size_t srow0 = (size_t)(step + 1) * MB + rowb;
                for (int idx = tid; idx < 32 * RW; idx += 256) {
                    int c4   = idx & 3;
                    int r    = (idx >> 2) % RW;
                    int rest = idx / (4 * RW);
                    int pl   = rest & 1;
                    int gg   = rest >> 1;
                    const float* src =
                        &g_xg[((size_t)(gg * 16 + cg * 2 + pl) * RTOT + srow0 + r) * 16
                              + c4 * 4];
                    float4 v = *(const float4*)src;
                    float* dst = &Xg[(gg * RW + r) * CWP + pl * 16 + c4 * 4];
                    dst[0] = v.x; dst[1] = v.y; dst[2] = v.z; dst[3] = v.w;
                }
            }
        }
    }
}

// ---------------------------------------------------------------------------
// kernel_launch: per layer: split-convert A & W -> HMMA GEMM -> zero_bar ->
// interleaved scan. Graph-capturable, allocation-free, deterministic.
// ---------------------------------------------------------------------------
extern "C" void kernel_launch(void* const* d_in, const int* in_sizes, int n_in,
                              void* d_out, int out_size)
{
    (void)in_sizes; (void)n_in; (void)out_size;
    const float* x    = (const float*)d_in[0];
    const float* Wih0 = (const float*)d_in[1];
    const float* Whh0 = (const float*)d_in[2];
    const float* bih0 = (const float*)d_in[3];
    const float* bhh0 = (const float*)d_in[4];
    const float* Wih1 = (const float*)d_in[5];
    const float* Whh1 = (const float*)d_in[6];
    const float* bih1 = (const float*)d_in[7];
    const float* bhh1 = (const float*)d_in[8];
    const float* Wih2 = (const float*)d_in[9];
    const float* Whh2 = (const float*)d_in[10];
    const float* bih2 = (const float*)d_in[11];
    const float* bhh2 = (const float*)d_in[12];
    float* out = (float*)d_out;

    float* tmp = nullptr;
    cudaGetSymbolAddress((void**)&tmp, g_tmp);
    __nv_bfloat16 *Ah = nullptr, *Al = nullptr, *Wh = nullptr, *Wl = nullptr;
    cudaGetSymbolAddress((void**)&Ah, g_Ah);
    cudaGetSymbolAddress((void**)&Al, g_Al);
    cudaGetSymbolAddress((void**)&Wh, g_Wh);
    cudaGetSymbolAddress((void**)&Wl, g_Wl);

    // Scan SMEM (floats): 4*32*SPAD + NG*RW*SPAD + NG*4*RW*36 + RW*36
    const int smA = (4 * 32 * SPAD + 2 * 8 * SPAD + 2 * 4 * 8 * 36 + 8 * 36) * 4;    // RW=8  -> 160128 B
    const int smB = (4 * 32 * SPAD + 2 * 16 * SPAD + 2 * 4 * 16 * 36 + 16 * 36) * 4; // RW=16 -> 187136 B
    cudaFuncSetAttribute((const void*)scan_kernel<128, 8, 2>,
                         cudaFuncAttributeMaxDynamicSharedMemorySize, smA);
    cudaFuncSetAttribute((const void*)scan_kernel<256, 8, 2>,
                         cudaFuncAttributeMaxDynamicSharedMemorySize, smA);
    cudaFuncSetAttribute((const void*)scan_kernel<512, 16, 2>,
                         cudaFuncAttributeMaxDynamicSharedMemorySize, smB);

    const int gsm = 1024 + 2 * 32768;
    cudaFuncSetAttribute((const void*)gemm_hmma_kernel<128>,
                         cudaFuncAttributeMaxDynamicSharedMemorySize, gsm);
    cudaFuncSetAttribute((const void*)gemm_hmma_kernel<256>,
                         cudaFuncAttributeMaxDynamicSharedMemorySize, gsm);

    dim3 ggrid(8, 1024);   // 128-col x 128-row tiles over [131072 x 1024]

    // ---- Layer 0: K=128, MB=128, 1024 steps. 64 blocks (8cg x 8 rg, NG=2)
    {
        int n4a = RTOT * 128 / 4;
        convert_split_kernel<<<(n4a + 255) / 256, 256>>>(x, Ah, Al, n4a);
        int n4w = 1024 * 128 / 4;
        convert_split_kernel<<<(n4w + 255) / 256, 256>>>(Wih0, Wh, Wl, n4w);
        gemm_hmma_kernel<128><<<ggrid, 256, gsm>>>(bih0, bhh0);
        zero_bar_kernel<<<1, 1024>>>();
        scan_kernel<128, 8, 2><<<8 * (128 / 16), 256, smA>>>(Whh0, tmp, 1024);
    }
    // ---- Layer 1: K=256, MB=256, 512 steps. 128 blocks (8cg x 16 rg, NG=2)
    {
        int n4a = RTOT * 256 / 4;
        convert_split_kernel<<<(n4a + 255) / 256, 256>>>(tmp, Ah, Al, n4a);
        int n4w = 1024 * 256 / 4;
        convert_split_kernel<<<(n4w + 255) / 256, 256>>>(Wih1, Wh, Wl, n4w);
        gemm_hmma_kernel<256><<<ggrid, 256, gsm>>>(bih1, bhh1);
        zero_bar_kernel<<<1, 1024>>>();
        scan_kernel<256, 8, 2><<<8 * (256 / 16), 256, smA>>>(Whh1, tmp, 512);
    }
    // ---- Layer 2: K=256, MB=512, 256 steps. 128 blocks (8cg x 16 rg, NG=2)
    {
        int n4a = RTOT * 256 / 4;
        convert_split_kernel<<<(n4a + 255) / 256, 256>>>(tmp, Ah, Al, n4a);
        int n4w = 1024 * 256 / 4;
        convert_split_kernel<<<(n4w + 255) / 256, 256>>>(Wih2, Wh, Wl, n4w);
        gemm_hmma_kernel<256><<<ggrid, 256, gsm>>>(bih2, bhh2);
        zero_bar_kernel<<<1, 1024>>>();
        scan_kernel<512, 16, 2><<<8 * (512 / 32), 256, smB>>>(Whh2, out, 256);
    }
}

// round 12
// speedup vs baseline: 1.7300x; 1.3647x over previous
#include <cuda_runtime.h>
#include <cuda_bf16.h>
#include <cstddef>
#include <cstdint>

// Problem constants
#define TT     1024
#define BBATCH 128
#define DD     128
#define HH     256
#define RTOT   (TT * BBATCH)   /* 131072 flat rows */
#define G4H    1024            /* 4*H gate columns */
#define SPAD   260             /* padded SMEM row stride (floats) */
#define BKC    64              /* GEMM K chunk in bf16 elements (128B rows) */

typedef unsigned long long ull;

// ---------------------------------------------------------------------------
// Scratch (static device globals -- no allocation APIs allowed)
// g_xg layout is PERMUTED for scan-side coalescing:
//   element (flat row r, gate col n) lives at ((n>>4)*RTOT + r)*16 + (n&15)
// ---------------------------------------------------------------------------
__device__ float g_xg[(size_t)RTOT * G4H];   // 512 MB gate staging (permuted)
__device__ float g_tmp[(size_t)RTOT * HH];   // 128 MB inter-layer activations
__device__ __align__(256) __nv_bfloat16 g_Ah[(size_t)RTOT * HH]; // 64 MB
__device__ __align__(256) __nv_bfloat16 g_Al[(size_t)RTOT * HH]; // 64 MB
__device__ __align__(256) __nv_bfloat16 g_Wh[1024 * HH];
__device__ __align__(256) __nv_bfloat16 g_Wl[1024 * HH];
// Per-row-group flag line: g_rgbar[rg*32 + cg] = number of steps block (cg,rg)
// has published. One 128B line per rg. Zeroed by zero_bar before every scan.
__device__ __align__(128) unsigned g_rgbar[16 * 32];

// ---------------------------------------------------------------------------
// Helpers (portable PTX only)
// ---------------------------------------------------------------------------
__device__ __forceinline__ void fma2(ull& d, ull a, ull b) {
    asm("fma.rn.f32x2 %0, %1, %2, %0;" : "+l"(d) : "l"(a), "l"(b));
}
__device__ __forceinline__ float2 unpack2(ull v) {
    unsigned lo, hi;
    asm("mov.b64 {%0, %1}, %2;" : "=r"(lo), "=r"(hi) : "l"(v));
    return make_float2(__uint_as_float(lo), __uint_as_float(hi));
}
__device__ __forceinline__ unsigned ld_acq(const unsigned* p) {
    unsigned v;
    asm volatile("ld.acquire.gpu.u32 %0, [%1];" : "=r"(v) : "l"(p) : "memory");
    return v;
}
__device__ __forceinline__ void st_rel(unsigned* p, unsigned v) {
    asm volatile("st.release.gpu.u32 [%0], %1;" :: "l"(p), "r"(v) : "memory");
}
__device__ __forceinline__ float sigf(float x) {
    return __fdividef(1.f, 1.f + __expf(-x));
}
__device__ __forceinline__ float tanh_fast(float x) {
    return 2.f * sigf(2.f * x) - 1.f;
}
__device__ __forceinline__ uint32_t smem_u32(const void* p) {
    uint32_t a;
    asm("{ .reg .u64 t; cvta.to.shared.u64 t, %1; cvt.u32.u64 %0, t; }"
        : "=r"(a) : "l"(p));
    return a;
}
#define SWZ(o) ((o) ^ (((o) >> 3) & 0x70))
__device__ __forceinline__ void cp16(uint32_t dst, const void* src) {
    asm volatile("cp.async.cg.shared.global [%0], [%1], 16;"
                 :: "r"(dst), "l"(src) : "memory");
}
__device__ __forceinline__ void ldm4(uint32_t* r, uint32_t addr) {
    asm volatile("ldmatrix.sync.aligned.m8n8.x4.shared.b16 {%0,%1,%2,%3}, [%4];"
                 : "=r"(r[0]), "=r"(r[1]), "=r"(r[2]), "=r"(r[3]) : "r"(addr));
}
__device__ __forceinline__ void mma_bf16(float* d, const uint32_t* a,
                                         const uint32_t* b) {
    asm volatile(
        "mma.sync.aligned.m16n8k16.row.col.f32.bf16.bf16.f32 "
        "{%0,%1,%2,%3}, {%4,%5,%6,%7}, {%8,%9}, {%0,%1,%2,%3};"
        : "+f"(d[0]), "+f"(d[1]), "+f"(d[2]), "+f"(d[3])
        : "r"(a[0]), "r"(a[1]), "r"(a[2]), "r"(a[3]), "r"(b[0]), "r"(b[1]));
}

// ---------------------------------------------------------------------------
// zero_bar: reset all flags (launched before each scan; kernel boundary = sync)
// ---------------------------------------------------------------------------
__global__ void zero_bar_kernel() {
    g_rgbar[threadIdx.x] = 0u;
}

// ---------------------------------------------------------------------------
// Split-conversion: fp32 -> (bf16 hi, bf16 lo). n4 = element count / 4.
// ---------------------------------------------------------------------------
__global__ void __launch_bounds__(256) convert_split_kernel(
    const float* __restrict__ src, __nv_bfloat16* __restrict__ hi,
    __nv_bfloat16* __restrict__ lo, int n4)
{
    int i = blockIdx.x * blockDim.x + threadIdx.x;
    if (i >= n4) return;
    float4 v = ((const float4*)src)[i];
    __nv_bfloat16 h0 = __float2bfloat16(v.x);
    __nv_bfloat16 h1 = __float2bfloat16(v.y);
    __nv_bfloat16 h2 = __float2bfloat16(v.z);
    __nv_bfloat16 h3 = __float2bfloat16(v.w);
    __nv_bfloat16 l0 = __float2bfloat16(v.x - __bfloat162float(h0));
    __nv_bfloat16 l1 = __float2bfloat16(v.y - __bfloat162float(h1));
    __nv_bfloat16 l2 = __float2bfloat16(v.z - __bfloat162float(h2));
    __nv_bfloat16 l3 = __float2bfloat16(v.w - __bfloat162float(h3));
    ((__nv_bfloat162*)hi)[2 * i]     = __nv_bfloat162(h0, h1);
    ((__nv_bfloat162*)hi)[2 * i + 1] = __nv_bfloat162(h2, h3);
    ((__nv_bfloat162*)lo)[2 * i]     = __nv_bfloat162(l0, l1);
    ((__nv_bfloat162*)lo)[2 * i + 1] = __nv_bfloat162(l2, l3);
}

// ---------------------------------------------------------------------------
// HMMA bf16-split GEMM (unchanged -- proven).
// xg[r][n] = sum_k A[r][k]*W[n][k] + bih[n]+bhh[n], output PERMUTED.
// ---------------------------------------------------------------------------
template <int K>
__global__ void __launch_bounds__(256) gemm_hmma_kernel(
    const float* __restrict__ bih, const float* __restrict__ bhh)
{
    extern __shared__ char smem[];
    const uint32_t abase = (smem_u32(smem) + 1023u) & ~1023u;

    const int tid  = threadIdx.x;
    const int wid  = tid >> 5;
    const int lane = tid & 31;
    const int col0 = blockIdx.x * 128;
    const int row0 = blockIdx.y * 128;
    const int wm   = wid & 1;
    const int wn   = wid >> 1;

    const __nv_bfloat16* Aop[3] = {g_Ah, g_Al, g_Ah};
    const __nv_bfloat16* Bop[3] = {g_Wh, g_Wh, g_Wl};
    constexpr int KCH = K / BKC;
    constexpr int NC  = 3 * KCH;

    auto prefetch = [&](int c) {
        const int pass = c / KCH;
        const int kc   = c % KCH;
        const __nv_bfloat16* A = Aop[pass];
        const __nv_bfloat16* B = Bop[pass];
        const uint32_t bufA = abase + (uint32_t)(c & 1) * 32768u;
        const uint32_t bufB = bufA + 16384u;
#pragma unroll
        for (int i = 0; i < 4; ++i) {
            int ch = tid + i * 256;
            int r  = ch >> 3;
            int cc = ch & 7;
            uint32_t off = SWZ((uint32_t)(r * 128 + cc * 16));
            cp16(bufA + off, A + (size_t)(row0 + r) * K + kc * BKC + cc * 8);
            cp16(bufB + off, B + (size_t)(col0 + r) * K + kc * BKC + cc * 8);
        }
        asm volatile("cp.async.commit_group;" ::: "memory");
    };

    float acc[4][4][4];
#pragma unroll
    for (int mt = 0; mt < 4; ++mt)
#pragma unroll
        for (int nt = 0; nt < 4; ++nt)
#pragma unroll
            for (int i = 0; i < 4; ++i) acc[mt][nt][i] = 0.f;

    prefetch(0);

    for (int c = 0; c < NC; ++c) {
        if (c + 1 < NC) {
            prefetch(c + 1);
            asm volatile("cp.async.wait_group 1;" ::: "memory");
        } else {
            asm volatile("cp.async.wait_group 0;" ::: "memory");
        }
        __syncthreads();

        const uint32_t bufA = abase + (uint32_t)(c & 1) * 32768u;
        const uint32_t bufB = bufA + 16384u;

#pragma unroll
        for (int ks = 0; ks < 4; ++ks) {
            uint32_t afr[4][4];
            {
                int arow = wm * 64 + (lane & 15);
                int kb   = ks * 32 + (lane >> 4) * 16;
#pragma unroll
                for (int mt = 0; mt < 4; ++mt)
                    ldm4(afr[mt],
                         bufA + SWZ((uint32_t)((arow + mt * 16) * 128 + kb)));
            }
            uint32_t bfr[4][2];
            {
                int j    = lane >> 3;
                int brow = (j >> 1) * 8 + (lane & 7);
                int kb   = ks * 32 + (j & 1) * 16;
#pragma unroll
                for (int p = 0; p < 2; ++p) {
                    uint32_t r[4];
                    ldm4(r, bufB +
                            SWZ((uint32_t)((wn * 32 + p * 16 + brow) * 128 + kb)));
                    bfr[p * 2][0]     = r[0];
                    bfr[p * 2][1]     = r[1];
                    bfr[p * 2 + 1][0] = r[2];
                    bfr[p * 2 + 1][1] = r[3];
                }
            }
#pragma unroll
            for (int mt = 0; mt < 4; ++mt)
#pragma unroll
                for (int nt = 0; nt < 4; ++nt)
                    mma_bf16(acc[mt][nt], afr[mt], bfr[nt]);
        }
        __syncthreads();
    }

#pragma unroll
    for (int nt = 0; nt < 4; ++nt) {
        int n0 = col0 + wn * 32 + nt * 8 + (lane & 3) * 2;
        float b0 = bih[n0] + bhh[n0];
        float b1 = bih[n0 + 1] + bhh[n0 + 1];
        size_t plane = (size_t)(n0 >> 4) * RTOT;
        int cc = n0 & 15;
#pragma unroll
        for (int mt = 0; mt < 4; ++mt) {
            int r0 = row0 + wm * 64 + mt * 16 + (lane >> 2);
            float2 v0 = make_float2(acc[mt][nt][0] + b0, acc[mt][nt][1] + b1);
            float2 v1 = make_float2(acc[mt][nt][2] + b0, acc[mt][nt][3] + b1);
            *(float2*)&g_xg[(plane + r0) * 16 + cc]     = v0;
            *(float2*)&g_xg[(plane + r0 + 8) * 16 + cc] = v1;
        }
    }
}

// ---------------------------------------------------------------------------
// Persistent scan (R6 structure) with flag-array barrier.
// 128 blocks: cg = bid%8 owns CW=32 h-columns, rg = bid/8 owns RW rows.
// Publish: after h stores land, tid0 does fence + st.release of flag
// g_rgbar[rg*32+cg] = step+1 (one word per producer -- no atomics, no relay).
// Wait: each staging thread polls ONLY the flag of the producer whose columns
// it loads (prod = (tid&63)>>3), so loads begin as soon as that producer
// lands; the pre-compute __syncthreads combines all conditions.
// Seeds (xg) are double-buffered in SMEM and prefetched in the publish shadow.
// ---------------------------------------------------------------------------
template <int MB, int RPT>
__global__ void __launch_bounds__(256, 1) scan_kernel(
    const float* __restrict__ Whh,   // [1024, 256] row-major
    float* __restrict__ out,         // [nsteps*MB, 256]
    int nsteps)
{
    constexpr int CW  = 32;
    constexpr int NCG = 8;
    constexpr int CWP = 36;
    constexpr int RPW = 8;
    constexpr int RW  = RPW * RPT;

    extern __shared__ float smemf[];
    float* Wsm = smemf;                       // [4*CW][SPAD]
    float* Hsm = Wsm + 4 * CW * SPAD;         // [RW][SPAD]
    float* Xsm = Hsm + RW * SPAD;             // [2][4][RW][CWP]
    float* Ssm = Xsm + 2 * 4 * RW * CWP;      // [RW][CWP]

    const int tid     = threadIdx.x;
    const int cg      = blockIdx.x % NCG;
    const int rg      = blockIdx.x / NCG;
    const int gc0     = cg * CW;
    const int rowbase = rg * RW;
    const int c       = tid >> 3;             // owned column 0..31
    const int q       = tid & 7;              // row slot 0..7
    const int prod    = (tid & 63) >> 3;      // producer of this thread's cols
    unsigned* myflag  = &g_rgbar[rg * 32 + cg];
    unsigned* pflag   = &g_rgbar[rg * 32 + prod];

    // Stage W slice (one-time): Wsm[gg*CW+cc][k] = Whh[gg*256+gc0+cc][k]
    for (int idx = tid; idx < 4 * CW * 64; idx += 256) {
        int k4 = idx & 63;
        int cc = (idx >> 6) & 31;
        int gg = idx >> 11;
        float4 v = *(const float4*)&Whh[(size_t)(gg * 256 + gc0 + cc) * HH + k4 * 4];
        *(float4*)&Wsm[(gg * CW + cc) * SPAD + k4 * 4] = v;
    }
    // Stage step-0 seeds into Xsm[0] (permuted g_xg: planes cg*2, cg*2+1)
    for (int idx = tid; idx < 32 * RW; idx += 256) {
        int c4   = idx & 3;
        int r    = (idx >> 2) % RW;
        int rest = idx / (4 * RW);
        int pl   = rest & 1;
        int gg   = rest >> 1;
        const float* src =
            &g_xg[((size_t)(gg * 16 + cg * 2 + pl) * RTOT + rowbase + r) * 16 + c4 * 4];
        float4 v = *(const float4*)src;
        float* dst = &Xsm[(gg * RW + r) * CWP + pl * 16 + c4 * 4];
        dst[0] = v.x; dst[1] = v.y; dst[2] = v.z; dst[3] = v.w;
    }

    float c_st[RPT];
#pragma unroll
    for (int j = 0; j < RPT; ++j) c_st[j] = 0.f;

    for (int step = 0; step < nsteps; ++step) {
        const int buf = step & 1;

        if (step > 0) {
            // Wait only for the producer whose columns this thread stages.
            while ((int)(ld_acq(pflag) - (unsigned)step) < 0) { }
            const float* hp = out + ((size_t)(step - 1) * MB + rowbase) * HH;
            for (int idx = tid; idx < RW * 64; idx += 256) {
                int r  = idx >> 6;
                int k4 = idx & 63;
                float4 v = *(const float4*)&hp[r * HH + k4 * 4];
                *(float4*)&Hsm[r * SPAD + k4 * 4] = v;
            }
        }
        __syncthreads();   // Hsm + Xsm[buf] ready

        const float* Xb = Xsm + buf * 4 * RW * CWP;
        ull acc[RPT][4];
#pragma unroll
        for (int j = 0; j < RPT; ++j)
#pragma unroll
            for (int gg = 0; gg < 4; ++gg) acc[j][gg] = 0ull;

        if (step > 0) {
#pragma unroll 2
            for (int k4 = 0; k4 < 64; ++k4) {
                ulonglong2 w[4];
#pragma unroll
                for (int gg = 0; gg < 4; ++gg)
                    w[gg] = *(const ulonglong2*)&Wsm[(gg * CW + c) * SPAD + k4 * 4];
#pragma unroll
                for (int j = 0; j < RPT; ++j) {
                    ulonglong2 h2 =
                        *(const ulonglong2*)&Hsm[(q + j * 8) * SPAD + k4 * 4];
#pragma unroll
                    for (int gg = 0; gg < 4; ++gg) {
                        fma2(acc[j][gg], h2.x, w[gg].x);
                        fma2(acc[j][gg], h2.y, w[gg].y);
                    }
                }
            }
        }

        // LSTM cell -> Ssm
#pragma unroll
        for (int j = 0; j < RPT; ++j) {
            int row = q + j * 8;
            float2 pi = unpack2(acc[j][0]);
            float2 pf = unpack2(acc[j][1]);
            float2 pg = unpack2(acc[j][2]);
            float2 po = unpack2(acc[j][3]);
            float vi = pi.x + pi.y + Xb[(0 * RW + row) * CWP + c];
            float vf = pf.x + pf.y + Xb[(1 * RW + row) * CWP + c];
            float vg = pg.x + pg.y + Xb[(2 * RW + row) * CWP + c];
            float vo = po.x + po.y + Xb[(3 * RW + row) * CWP + c];
            float ig = sigf(vi);
            float fg = sigf(vf);
            float gt = tanh_fast(vg);
            float og = sigf(vo);
            float cc2 = fg * c_st[j] + ig * gt;
            c_st[j] = cc2;
            Ssm[row * CWP + c] = og * tanh_fast(cc2);
        }
        __syncthreads();   // Ssm ready; Hsm/Xsm[buf] reads done

        // Publish h (layer output AND exchange medium), coalesced
        {
            const size_t ob = ((size_t)step * MB + rowbase) * HH + gc0;
            for (int idx = tid; idx < RW * 8; idx += 256) {
                int r  = idx >> 3;
                int c4 = idx & 7;
                const float* s = &Ssm[r * CWP + c4 * 4];
                float4 v = make_float4(s[0], s[1], s[2], s[3]);
                *(float4*)&out[ob + (size_t)r * HH + c4 * 4] = v;
            }
        }
        __syncthreads();   // all h stores issued block-wide

        if (step + 1 < nsteps) {
            if (tid == 0) {
                __threadfence();
                st_rel(myflag, (unsigned)(step + 1));
            }
            // Prefetch next step's seeds into alternate buffer (flag shadow)
            const size_t srow0 = (size_t)(step + 1) * MB + rowbase;
            float* Xn = Xsm + (1 - buf) * 4 * RW * CWP;
            for (int idx = tid; idx < 32 * RW; idx += 256) {
                int c4   = idx & 3;
                int r    = (idx >> 2) % RW;
                int rest = idx / (4 * RW);
                int pl   = rest & 1;
                int gg   = rest >> 1;
                const float* src =
                    &g_xg[((size_t)(gg * 16 + cg * 2 + pl) * RTOT + srow0 + r) * 16
                          + c4 * 4];
                float4 v = *(const float4*)src;
                float* dst = &Xn[(gg * RW + r) * CWP + pl * 16 + c4 * 4];
                dst[0] = v.x; dst[1] = v.y; dst[2] = v.z; dst[3] = v.w;
            }
        }
    }
}

// ---------------------------------------------------------------------------
// kernel_launch: per layer: split-convert A & W -> HMMA GEMM -> zero_bar ->
// scan. Graph-capturable, allocation-free, deterministic.
// ---------------------------------------------------------------------------
extern "C" void kernel_launch(void* const* d_in, const int* in_sizes, int n_in,
                              void* d_out, int out_size)
{
    (void)in_sizes; (void)n_in; (void)out_size;
    const float* x    = (const float*)d_in[0];
    const float* Wih0 = (const float*)d_in[1];
    const float* Whh0 = (const float*)d_in[2];
    const float* bih0 = (const float*)d_in[3];
    const float* bhh0 = (const float*)d_in[4];
    const float* Wih1 = (const float*)d_in[5];
    const float* Whh1 = (const float*)d_in[6];
    const float* bih1 = (const float*)d_in[7];
    const float* bhh1 = (const float*)d_in[8];
    const float* Wih2 = (const float*)d_in[9];
    const float* Whh2 = (const float*)d_in[10];
    const float* bih2 = (const float*)d_in[11];
    const float* bhh2 = (const float*)d_in[12];
    float* out = (float*)d_out;

    float* tmp = nullptr;
    cudaGetSymbolAddress((void**)&tmp, g_tmp);
    __nv_bfloat16 *Ah = nullptr, *Al = nullptr, *Wh = nullptr, *Wl = nullptr;
    cudaGetSymbolAddress((void**)&Ah, g_Ah);
    cudaGetSymbolAddress((void**)&Al, g_Al);
    cudaGetSymbolAddress((void**)&Wh, g_Wh);
    cudaGetSymbolAddress((void**)&Wl, g_Wl);

    // Scan SMEM (floats): 4*32*SPAD + RW*SPAD + 2*4*RW*36 + RW*36
    const int sm0 = (4 * 32 * SPAD + 8 * SPAD + 8 * 8 * 36 + 8 * 36) * 4;     // RW=8  -> 151808 B
    const int sm1 = (4 * 32 * SPAD + 16 * SPAD + 8 * 16 * 36 + 16 * 36) * 4;  // RW=16 -> 170496 B
    const int sm2 = (4 * 32 * SPAD + 32 * SPAD + 8 * 32 * 36 + 32 * 36) * 4;  // RW=32 -> 207872 B
    cudaFuncSetAttribute((const void*)scan_kernel<128, 1>,
                         cudaFuncAttributeMaxDynamicSharedMemorySize, sm0);
    cudaFuncSetAttribute((const void*)scan_kernel<256, 2>,
                         cudaFuncAttributeMaxDynamicSharedMemorySize, sm1);
    cudaFuncSetAttribute((const void*)scan_kernel<512, 4>,
                         cudaFuncAttributeMaxDynamicSharedMemorySize, sm2);

    const int gsm = 1024 + 2 * 32768;
    cudaFuncSetAttribute((const void*)gemm_hmma_kernel<128>,
                         cudaFuncAttributeMaxDynamicSharedMemorySize, gsm);
    cudaFuncSetAttribute((const void*)gemm_hmma_kernel<256>,
                         cudaFuncAttributeMaxDynamicSharedMemorySize, gsm);

    dim3 ggrid(8, 1024);   // 128-col x 128-row tiles over [131072 x 1024]

    // ---- Layer 0: K=128, MB=128, 1024 steps. 128 blocks (8cg x 16rg)
    {
        int n4a = RTOT * 128 / 4;
        convert_split_kernel<<<(n4a + 255) / 256, 256>>>(x, Ah, Al, n4a);
        int n4w = 1024 * 128 / 4;
        convert_split_kernel<<<(n4w + 255) / 256, 256>>>(Wih0, Wh, Wl, n4w);
        gemm_hmma_kernel<128><<<ggrid, 256, gsm>>>(bih0, bhh0);
        zero_bar_kernel<<<1, 512>>>();
        scan_kernel<128, 1><<<128, 256, sm0>>>(Whh0, tmp, 1024);
    }
    // ---- Layer 1: K=256, MB=256, 512 steps. 128 blocks
    {
        int n4a = RTOT * 256 / 4;
        convert_split_kernel<<<(n4a + 255) / 256, 256>>>(tmp, Ah, Al, n4a);
        int n4w = 1024 * 256 / 4;
        convert_split_kernel<<<(n4w + 255) / 256, 256>>>(Wih1, Wh, Wl, n4w);
        gemm_hmma_kernel<256><<<ggrid, 256, gsm>>>(bih1, bhh1);
        zero_bar_kernel<<<1, 512>>>();
        scan_kernel<256, 2><<<128, 256, sm1>>>(Whh1, tmp, 512);
    }
    // ---- Layer 2: K=256, MB=512, 256 steps. 128 blocks (final output)
    {
        int n4a = RTOT * 256 / 4;
        convert_split_kernel<<<(n4a + 255) / 256, 256>>>(tmp, Ah, Al, n4a);
        int n4w = 1024 * 256 / 4;
        convert_split_kernel<<<(n4w + 255) / 256, 256>>>(Wih2, Wh, Wl, n4w);
        gemm_hmma_kernel<256><<<ggrid, 256, gsm>>>(bih2, bhh2);
        zero_bar_kernel<<<1, 512>>>();
        scan_kernel<512, 4><<<128, 256, sm2>>>(Whh2, out, 256);
    }
}

// round 14
// speedup vs baseline: 1.8368x; 1.0617x over previous
#include <cuda_runtime.h>
#include <cuda_bf16.h>
#include <cstddef>
#include <cstdint>

// Problem constants
#define TT     1024
#define BBATCH 128
#define DD     128
#define HH     256
#define RTOT   (TT * BBATCH)   /* 131072 flat rows */
#define G4H    1024            /* 4*H gate columns */
#define SPAD   260             /* padded SMEM row stride (floats) */
#define BKC    64              /* GEMM K chunk in bf16 elements (128B rows) */

typedef unsigned long long ull;

// ---------------------------------------------------------------------------
// Scratch (static device globals -- no allocation APIs allowed)
// g_xg layout is PERMUTED for scan-side coalescing:
//   element (flat row r, gate col n) lives at ((n>>4)*RTOT + r)*16 + (n&15)
// ---------------------------------------------------------------------------
__device__ float g_xg[(size_t)RTOT * G4H];   // 512 MB gate staging (permuted)
__device__ float g_tmp[(size_t)RTOT * HH];   // 128 MB inter-layer activations
__device__ __align__(256) __nv_bfloat16 g_Ah[(size_t)RTOT * HH]; // 64 MB
__device__ __align__(256) __nv_bfloat16 g_Al[(size_t)RTOT * HH]; // 64 MB
__device__ __align__(256) __nv_bfloat16 g_Wh[1024 * HH];
__device__ __align__(256) __nv_bfloat16 g_Wl[1024 * HH];
// Per-row-group barrier state: [rg*64+0] = cnt, [rg*64+32] = gen (separate
// 128B lines). Sense-relative (base read per launch) + cnt self-resets =>
// deterministic across graph replays.
__device__ __align__(128) unsigned g_rgbar[16 * 64];

// ---------------------------------------------------------------------------
// Helpers (portable PTX only)
// ---------------------------------------------------------------------------
__device__ __forceinline__ void fma2(ull& d, ull a, ull b) {
    asm("fma.rn.f32x2 %0, %1, %2, %0;" : "+l"(d) : "l"(a), "l"(b));
}
__device__ __forceinline__ float2 unpack2(ull v) {
    unsigned lo, hi;
    asm("mov.b64 {%0, %1}, %2;" : "=r"(lo), "=r"(hi) : "l"(v));
    return make_float2(__uint_as_float(lo), __uint_as_float(hi));
}
__device__ __forceinline__ unsigned ld_acq(const unsigned* p) {
    unsigned v;
    asm volatile("ld.acquire.gpu.u32 %0, [%1];" : "=r"(v) : "l"(p) : "memory");
    return v;
}
__device__ __forceinline__ float sigf(float x) {
    return __fdividef(1.f, 1.f + __expf(-x));
}
__device__ __forceinline__ float tanh_fast(float x) {
    return 2.f * sigf(2.f * x) - 1.f;
}
__device__ __forceinline__ uint32_t smem_u32(const void* p) {
    uint32_t a;
    asm("{ .reg .u64 t; cvta.to.shared.u64 t, %1; cvt.u32.u64 %0, t; }"
        : "=r"(a) : "l"(p));
    return a;
}
#define SWZ(o) ((o) ^ (((o) >> 3) & 0x70))
__device__ __forceinline__ void cp16(uint32_t dst, const void* src) {
    asm volatile("cp.async.cg.shared.global [%0], [%1], 16;"
                 :: "r"(dst), "l"(src) : "memory");
}
__device__ __forceinline__ void ldm4(uint32_t* r, uint32_t addr) {
    asm volatile("ldmatrix.sync.aligned.m8n8.x4.shared.b16 {%0,%1,%2,%3}, [%4];"
                 : "=r"(r[0]), "=r"(r[1]), "=r"(r[2]), "=r"(r[3]) : "r"(addr));
}
__device__ __forceinline__ void mma_bf16(float* d, const uint32_t* a,
                                         const uint32_t* b) {
    asm volatile(
        "mma.sync.aligned.m16n8k16.row.col.f32.bf16.bf16.f32 "
        "{%0,%1,%2,%3}, {%4,%5,%6,%7}, {%8,%9}, {%0,%1,%2,%3};"
        : "+f"(d[0]), "+f"(d[1]), "+f"(d[2]), "+f"(d[3])
        : "r"(a[0]), "r"(a[1]), "r"(a[2]), "r"(a[3]), "r"(b[0]), "r"(b[1]));
}

// ---------------------------------------------------------------------------
// Split-conversion: fp32 -> (bf16 hi, bf16 lo). n4 = element count / 4.
// (used for the network input x and the weight matrices only; activation
//  conversion is fused into the scan publish)
// ---------------------------------------------------------------------------
__global__ void __launch_bounds__(256) convert_split_kernel(
    const float* __restrict__ src, __nv_bfloat16* __restrict__ hi,
    __nv_bfloat16* __restrict__ lo, int n4)
{
    int i = blockIdx.x * blockDim.x + threadIdx.x;
    if (i >= n4) return;
    float4 v = ((const float4*)src)[i];
    __nv_bfloat16 h0 = __float2bfloat16(v.x);
    __nv_bfloat16 h1 = __float2bfloat16(v.y);
    __nv_bfloat16 h2 = __float2bfloat16(v.z);
    __nv_bfloat16 h3 = __float2bfloat16(v.w);
    __nv_bfloat16 l0 = __float2bfloat16(v.x - __bfloat162float(h0));
    __nv_bfloat16 l1 = __float2bfloat16(v.y - __bfloat162float(h1));
    __nv_bfloat16 l2 = __float2bfloat16(v.z - __bfloat162float(h2));
    __nv_bfloat16 l3 = __float2bfloat16(v.w - __bfloat162float(h3));
    ((__nv_bfloat162*)hi)[2 * i]     = __nv_bfloat162(h0, h1);
    ((__nv_bfloat162*)hi)[2 * i + 1] = __nv_bfloat162(h2, h3);
    ((__nv_bfloat162*)lo)[2 * i]     = __nv_bfloat162(l0, l1);
    ((__nv_bfloat162*)lo)[2 * i + 1] = __nv_bfloat162(l2, l3);
}

// ---------------------------------------------------------------------------
// HMMA bf16-split GEMM (unchanged -- proven).
// xg[r][n] = sum_k A[r][k]*W[n][k] + bih[n]+bhh[n], output PERMUTED.
// ---------------------------------------------------------------------------
template <int K>
__global__ void __launch_bounds__(256) gemm_hmma_kernel(
    const float* __restrict__ bih, const float* __restrict__ bhh)
{
    extern __shared__ char smem[];
    const uint32_t abase = (smem_u32(smem) + 1023u) & ~1023u;

    const int tid  = threadIdx.x;
    const int wid  = tid >> 5;
    const int lane = tid & 31;
    const int col0 = blockIdx.x * 128;
    const int row0 = blockIdx.y * 128;
    const int wm   = wid & 1;
    const int wn   = wid >> 1;

    const __nv_bfloat16* Aop[3] = {g_Ah, g_Al, g_Ah};
    const __nv_bfloat16* Bop[3] = {g_Wh, g_Wh, g_Wl};
    constexpr int KCH = K / BKC;
    constexpr int NC  = 3 * KCH;

    auto prefetch = [&](int c) {
        const int pass = c / KCH;
        const int kc   = c % KCH;
        const __nv_bfloat16* A = Aop[pass];
        const __nv_bfloat16* B = Bop[pass];
        const uint32_t bufA = abase + (uint32_t)(c & 1) * 32768u;
        const uint32_t bufB = bufA + 16384u;
#pragma unroll
        for (int i = 0; i < 4; ++i) {
            int ch = tid + i * 256;
            int r  = ch >> 3;
            int cc = ch & 7;
            uint32_t off = SWZ((uint32_t)(r * 128 + cc * 16));
            cp16(bufA + off, A + (size_t)(row0 + r) * K + kc * BKC + cc * 8);
            cp16(bufB + off, B + (size_t)(col0 + r) * K + kc * BKC + cc * 8);
        }
        asm volatile("cp.async.commit_group;" ::: "memory");
    };

    float acc[4][4][4];
#pragma unroll
    for (int mt = 0; mt < 4; ++mt)
#pragma unroll
        for (int nt = 0; nt < 4; ++nt)
#pragma unroll
            for (int i = 0; i < 4; ++i) acc[mt][nt][i] = 0.f;

    prefetch(0);

    for (int c = 0; c < NC; ++c) {
        if (c + 1 < NC) {
            prefetch(c + 1);
            asm volatile("cp.async.wait_group 1;" ::: "memory");
        } else {
            asm volatile("cp.async.wait_group 0;" ::: "memory");
        }
        __syncthreads();

        const uint32_t bufA = abase + (uint32_t)(c & 1) * 32768u;
        const uint32_t bufB = bufA + 16384u;

#pragma unroll
        for (int ks = 0; ks < 4; ++ks) {
            uint32_t afr[4][4];
            {
                int arow = wm * 64 + (lane & 15);
                int kb   = ks * 32 + (lane >> 4) * 16;
#pragma unroll
                for (int mt = 0; mt < 4; ++mt)
                    ldm4(afr[mt],
                         bufA + SWZ((uint32_t)((arow + mt * 16) * 128 + kb)));
            }
            uint32_t bfr[4][2];
            {
                int j    = lane >> 3;
                int brow = (j >> 1) * 8 + (lane & 7);
                int kb   = ks * 32 + (j & 1) * 16;
#pragma unroll
                for (int p = 0; p < 2; ++p) {
                    uint32_t r[4];
                    ldm4(r, bufB +
                            SWZ((uint32_t)((wn * 32 + p * 16 + brow) * 128 + kb)));
                    bfr[p * 2][0]     = r[0];
                    bfr[p * 2][1]     = r[1];
                    bfr[p * 2 + 1][0] = r[2];
                    bfr[p * 2 + 1][1] = r[3];
                }
            }
#pragma unroll
            for (int mt = 0; mt < 4; ++mt)
#pragma unroll
                for (int nt = 0; nt < 4; ++nt)
                    mma_bf16(acc[mt][nt], afr[mt], bfr[nt]);
        }
        __syncthreads();
    }

#pragma unroll
    for (int nt = 0; nt < 4; ++nt) {
        int n0 = col0 + wn * 32 + nt * 8 + (lane & 3) * 2;
        float b0 = bih[n0] + bhh[n0];
        float b1 = bih[n0 + 1] + bhh[n0 + 1];
        size_t plane = (size_t)(n0 >> 4) * RTOT;
        int cc = n0 & 15;
#pragma unroll
        for (int mt = 0; mt < 4; ++mt) {
            int r0 = row0 + wm * 64 + mt * 16 + (lane >> 2);
            float2 v0 = make_float2(acc[mt][nt][0] + b0, acc[mt][nt][1] + b1);
            float2 v1 = make_float2(acc[mt][nt][2] + b0, acc[mt][nt][3] + b1);
            *(float2*)&g_xg[(plane + r0) * 16 + cc]     = v0;
            *(float2*)&g_xg[(plane + r0 + 8) * 16 + cc] = v1;
        }
    }
}

// ---------------------------------------------------------------------------
// Persistent recurrent scan (exact R6 structure) + two surgical deltas:
//   (1) only warp 0 polls the row-group generation, then __syncthreads
//       (leader-acquire + CTA-barrier pattern; 8x fewer L2 pollers)
//   (2) BF16OUT: publish also writes bf16 hi/lo splits of h directly into
//       g_Ah/g_Al (bit-identical to convert_split_kernel), removing the
//       standalone activation-convert launches.
// Block (cg, rg): cg = bid % NCG owns CW h-columns, rg = bid / NCG owns RW
// contiguous rows. Per-rg counting barrier, sense-relative.
// ---------------------------------------------------------------------------
template <int MB, int CW, int RPT, bool BF16OUT>
__global__ void __launch_bounds__(256, 1) scan_kernel(
    const float* __restrict__ Whh,   // [1024, 256] row-major
    float* __restrict__ out,         // [nsteps*MB, 256]
    int nsteps)
{
    constexpr int RPW = 256 / CW;        // row slots per column
    constexpr int RW  = RPW * RPT;       // rows per block
    constexpr int NCG = 256 / CW;        // column groups = barrier group size
    constexpr int CWP = (CW == 16) ? 18 : 36;  // conflict-free padded stride
    constexpr int NSL = CW / 16;         // 16-col planes per block

    extern __shared__ float smemf[];
    float* Wsm = smemf;                          // [4*CW][SPAD]
    float* Hsm = Wsm + 4 * CW * SPAD;            // [RW][SPAD]
    float* Xsm = Hsm + RW * SPAD;                // [2][4][RW][CWP]
    float* Ssm = Xsm + 2 * 4 * RW * CWP;         // [RW][CWP]

    const int tid     = threadIdx.x;
    const int cg      = blockIdx.x % NCG;
    const int rg      = blockIdx.x / NCG;
    const int gc0     = cg * CW;
    const int rowbase = rg * RW;
    const int c       = tid / RPW;       // owned column (0..CW-1)
    const int q       = tid % RPW;       // row slot

    unsigned* bcnt = &g_rgbar[rg * 64];
    unsigned* bgen = &g_rgbar[rg * 64 + 32];
    // Safe: this rg's gen cannot advance until THIS block arrives.
    const unsigned gbase = ld_acq(bgen);

    for (int idx = tid; idx < 4 * CW * 64; idx += 256) {
        int k4 = idx % 64;
        int cc = (idx / 64) % CW;
        int g  = idx / (64 * CW);
        float4 v = *(const float4*)&Whh[(size_t)(g * 256 + gc0 + cc) * HH + k4 * 4];
        *(float4*)&Wsm[(g * CW + cc) * SPAD + k4 * 4] = v;
    }

    // Pre-stage step-0 seeds into Xsm[0]
    {
        for (int idx = tid; idx < 4 * NSL * RW * 4; idx += 256) {
            int c4   = idx & 3;
            int r    = (idx >> 2) % RW;
            int rest = idx / (4 * RW);
            int cgi  = rest % NSL;
            int g    = rest / NSL;
            const float* src =
                &g_xg[((size_t)(g * 16 + cg * NSL + cgi) * RTOT + rowbase + r) * 16
                      + c4 * 4];
            float4 v = *(const float4*)src;
            float* dst = &Xsm[(g * RW + r) * CWP + cgi * 16 + c4 * 4];
            dst[0] = v.x; dst[1] = v.y; dst[2] = v.z; dst[3] = v.w;
        }
    }

    float c_st[RPT];
#pragma unroll
    for (int j = 0; j < RPT; ++j) c_st[j] = 0.f;

    for (int step = 0; step < nsteps; ++step) {
        const int buf = step & 1;

        if (step > 0) {
            // DELTA 1: only warp 0 polls the row-group generation.
            const unsigned target = gbase + (unsigned)step;
            if (tid < 32) {
                while ((int)(ld_acq(bgen) - target) < 0) { }
            }
            __syncthreads();
            // Stage h_prev slab (coalesced float4)
            const float* hp = out + ((size_t)(step - 1) * MB + rowbase) * HH;
            for (int idx = tid; idx < RW * 64; idx += 256) {
                int r  = idx / 64;
                int k4 = idx % 64;
                float4 v = *(const float4*)&hp[r * HH + k4 * 4];
                *(float4*)&Hsm[r * SPAD + k4 * 4] = v;
            }
        }
        __syncthreads();   // Hsm + Xsm[buf] ready

        const float* Xb = Xsm + buf * 4 * RW * CWP;
        ull acc[RPT][4];
#pragma unroll
        for (int j = 0; j < RPT; ++j)
#pragma unroll
            for (int g = 0; g < 4; ++g)
                acc[j][g] =
                    (ull)__float_as_uint(Xb[(g * RW + q + j * RPW) * CWP + c]);

        if (step > 0) {
#pragma unroll 2
            for (int k4 = 0; k4 < 64; ++k4) {
                ulonglong2 w[4];
#pragma unroll
                for (int g = 0; g < 4; ++g)
                    w[g] = *(const ulonglong2*)&Wsm[(g * CW + c) * SPAD + k4 * 4];
#pragma unroll
                for (int j = 0; j < RPT; ++j) {
                    ulonglong2 h2 =
                        *(const ulonglong2*)&Hsm[(q + j * RPW) * SPAD + k4 * 4];
#pragma unroll
                    for (int g = 0; g < 4; ++g) {
                        fma2(acc[j][g], h2.x, w[g].x);
                        fma2(acc[j][g], h2.y, w[g].y);
                    }
                }
            }
        }

        // LSTM cell -> stage h into Ssm
#pragma unroll
        for (int j = 0; j < RPT; ++j) {
            float2 pi = unpack2(acc[j][0]);
            float2 pf = unpack2(acc[j][1]);
            float2 pg = unpack2(acc[j][2]);
            float2 po = unpack2(acc[j][3]);
            float vi = pi.x + pi.y;
            float vf = pf.x + pf.y;
            float vg = pg.x + pg.y;
            float vo = po.x + po.y;
            float ig = sigf(vi);
            float fg = sigf(vf);
            float gt = tanh_fast(vg);
            float og = sigf(vo);
            float cc2 = fg * c_st[j] + ig * gt;
            c_st[j] = cc2;
            Ssm[(q + j * RPW) * CWP + c] = og * tanh_fast(cc2);
        }
        __syncthreads();   // Ssm ready; Hsm/Xsm[buf] reads done

        // Coalesced h store (fp32 exchange) + DELTA 2: fused bf16 hi/lo split
        {
            const size_t rowflat = (size_t)step * MB + rowbase;
            float* orow = out + rowflat * HH + gc0;
            for (int idx = tid; idx < RW * (CW / 4); idx += 256) {
                int c4 = idx % (CW / 4);
                int r  = idx / (CW / 4);
                const float* s = &Ssm[r * CWP + c4 * 4];
                float4 v = make_float4(s[0], s[1], s[2], s[3]);
                *(float4*)&orow[(size_t)r * HH + c4 * 4] = v;
                if (BF16OUT) {
                    __nv_bfloat16 h0 = __float2bfloat16(v.x);
                    __nv_bfloat16 h1 = __float2bfloat16(v.y);
                    __nv_bfloat16 h2 = __float2bfloat16(v.z);
                    __nv_bfloat16 h3 = __float2bfloat16(v.w);
                    __nv_bfloat16 l0 = __float2bfloat16(v.x - __bfloat162float(h0));
                    __nv_bfloat16 l1 = __float2bfloat16(v.y - __bfloat162float(h1));
                    __nv_bfloat16 l2 = __float2bfloat16(v.z - __bfloat162float(h2));
                    __nv_bfloat16 l3 = __float2bfloat16(v.w - __bfloat162float(h3));
                    size_t ab = (rowflat + r) * HH + gc0 + c4 * 4;
                    *(__nv_bfloat162*)&g_Ah[ab]     = __nv_bfloat162(h0, h1);
                    *(__nv_bfloat162*)&g_Ah[ab + 2] = __nv_bfloat162(h2, h3);
                    *(__nv_bfloat162*)&g_Al[ab]     = __nv_bfloat162(l0, l1);
                    *(__nv_bfloat162*)&g_Al[ab + 2] = __nv_bfloat162(l2, l3);
                }
            }
        }
        __syncthreads();   // all h stores issued, block-visible

        if (step + 1 < nsteps) {
            // Release-arrive on the row-group barrier (thread 0)
            if (tid == 0) {
                __threadfence();
                if (atomicAdd(bcnt, 1u) == (unsigned)(NCG - 1)) {
                    atomicExch(bcnt, 0u);
                    __threadfence();
                    atomicAdd(bgen, 1u);
                }
            }
            // Prefetch next step's seeds into the alternate buffer while the
            // row-group barrier drains (off the critical path).
            const size_t srow0 = (size_t)(step + 1) * MB + rowbase;
            float* Xn = Xsm + (1 - buf) * 4 * RW * CWP;
            for (int idx = tid; idx < 4 * NSL * RW * 4; idx += 256) {
                int c4   = idx & 3;
                int r    = (idx >> 2) % RW;
                int rest = idx / (4 * RW);
                int cgi  = rest % NSL;
                int g    = rest / NSL;
                const float* src =
                    &g_xg[((size_t)(g * 16 + cg * NSL + cgi) * RTOT + srow0 + r) * 16
                          + c4 * 4];
                float4 v = *(const float4*)src;
                float* dst = &Xn[(g * RW + r) * CWP + cgi * 16 + c4 * 4];
                dst[0] = v.x; dst[1] = v.y; dst[2] = v.z; dst[3] = v.w;
            }
        }
    }
}

// ---------------------------------------------------------------------------
// kernel_launch: per layer: (converts) -> HMMA GEMM -> scan (which itself
// emits the next layer's bf16 activations). Graph-capturable, allocation-
// free, deterministic.
// ---------------------------------------------------------------------------
extern "C" void kernel_launch(void* const* d_in, const int* in_sizes, int n_in,
                              void* d_out, int out_size)
{
    (void)in_sizes; (void)n_in; (void)out_size;
    const float* x    = (const float*)d_in[0];
    const float* Wih0 = (const float*)d_in[1];
    const float* Whh0 = (const float*)d_in[2];
    const float* bih0 = (const float*)d_in[3];
    const float* bhh0 = (const float*)d_in[4];
    const float* Wih1 = (const float*)d_in[5];
    const float* Whh1 = (const float*)d_in[6];
    const float* bih1 = (const float*)d_in[7];
    const float* bhh1 = (const float*)d_in[8];
    const float* Wih2 = (const float*)d_in[9];
    const float* Whh2 = (const float*)d_in[10];
    const float* bih2 = (const float*)d_in[11];
    const float* bhh2 = (const float*)d_in[12];
    float* out = (float*)d_out;

    float* tmp = nullptr;
    cudaGetSymbolAddress((void**)&tmp, g_tmp);
    __nv_bfloat16 *Ah = nullptr, *Al = nullptr, *Wh = nullptr, *Wl = nullptr;
    cudaGetSymbolAddress((void**)&Ah, g_Ah);
    cudaGetSymbolAddress((void**)&Al, g_Al);
    cudaGetSymbolAddress((void**)&Wh, g_Wh);
    cudaGetSymbolAddress((void**)&Wl, g_Wl);

    // Scan SMEM: (4*CW + RW)*SPAD + 9*RW*CWP floats
    const int smem0 = ((4 * 16 + 16) * SPAD + 9 * 16 * 18) * 4;
    const int smem1 = ((4 * 32 + 16) * SPAD + 9 * 16 * 36) * 4;
    const int smem2 = ((4 * 32 + 32) * SPAD + 9 * 32 * 36) * 4;
    cudaFuncSetAttribute((const void*)scan_kernel<128, 16, 1, true>,
                         cudaFuncAttributeMaxDynamicSharedMemorySize, smem0);
    cudaFuncSetAttribute((const void*)scan_kernel<256, 32, 2, true>,
                         cudaFuncAttributeMaxDynamicSharedMemorySize, smem1);
    cudaFuncSetAttribute((const void*)scan_kernel<512, 32, 4, false>,
                         cudaFuncAttributeMaxDynamicSharedMemorySize, smem2);

    const int gsm = 1024 + 2 * 32768;
    cudaFuncSetAttribute((const void*)gemm_hmma_kernel<128>,
                         cudaFuncAttributeMaxDynamicSharedMemorySize, gsm);
    cudaFuncSetAttribute((const void*)gemm_hmma_kernel<256>,
                         cudaFuncAttributeMaxDynamicSharedMemorySize, gsm);

    dim3 ggrid(8, 1024);   // 128-col x 128-row tiles over [131072 x 1024]

    // ---- Layer 0: K=128, MB=128, 1024 steps
    {
        int n4a = RTOT * 128 / 4;
        convert_split_kernel<<<(n4a + 255) / 256, 256>>>(x, Ah, Al, n4a);
        int n4w = 1024 * 128 / 4;
        convert_split_kernel<<<(n4w + 255) / 256, 256>>>(Wih0, Wh, Wl, n4w);
        gemm_hmma_kernel<128><<<ggrid, 256, gsm>>>(bih0, bhh0);
        scan_kernel<128, 16, 1, true><<<128, 256, smem0>>>(Whh0, tmp, 1024);
    }
    // ---- Layer 1: K=256, MB=256, 512 steps (A bf16 produced by scan 0)
    {
        int n4w = 1024 * 256 / 4;
        convert_split_kernel<<<(n4w + 255) / 256, 256>>>(Wih1, Wh, Wl, n4w);
        gemm_hmma_kernel<256><<<ggrid, 256, gsm>>>(bih1, bhh1);
        scan_kernel<256, 32, 2, true><<<128, 256, smem1>>>(Whh1, tmp, 512);
    }
    // ---- Layer 2: K=256, MB=512, 256 steps (A bf16 produced by scan 1)
    {
        int n4w = 1024 * 256 / 4;
        convert_split_kernel<<<(n4w + 255) / 256, 256>>>(Wih2, Wh, Wl, n4w);
        gemm_hmma_kernel<256><<<ggrid, 256, gsm>>>(bih2, bhh2);
        scan_kernel<512, 32, 4, false><<<128, 256, smem2>>>(Whh2, out, 256);
    }
}